// round 14
// baseline (speedup 1.0000x reference)
#include <cuda_runtime.h>

// CRF NLL: 3-segment rank-1 split (R12) + consume-time-exp raw feats ring
// (R13 fix) + __launch_bounds__(32,14) so all 2048 single-warp blocks fit
// in ONE wave (<=146 regs -> 14 blocks/SM). Depth ~L/3 (<=171 steps).
// Z = (t^T u)(v^T P)/(e^T u), roles:
//   0: P = M(1,a) P0       (fwd, E^T)   1: u = M(a+1,b) e    (fwd, E^T)
//   2: v = M(a+1,b)^T e    (bwd, E)     3: t = M(b+1,L-1)^T Estop (bwd, E)
// Exact power-of-2 rescaling; no CTA barriers.

constexpr int Bb = 512;
constexpr int Ss = 512;
constexpr int Tt = 64;
constexpr int START = Tt - 2;
constexpr int STOP  = Tt - 1;
constexpr int PD    = 4;
constexpr float LN2 = 0.69314718055994531f;

__device__ __align__(16) float g_expE [Tt * Tt];   // exp(trans) [from][to]
__device__ __align__(16) float g_expET[Tt * Tt];   // transpose  [to][from]
__device__ float g_meet[Bb][4][68];
__device__ float g_partial[Bb];
__device__ unsigned g_pair[Bb];
__device__ unsigned g_count = 0;

typedef unsigned long long u64;

static __device__ __forceinline__ u64 fma2(u64 a, u64 b, u64 c) {
    u64 d;
    asm("fma.rn.f32x2 %0, %1, %2, %3;" : "=l"(d) : "l"(a), "l"(b), "l"(c));
    return d;
}
static __device__ __forceinline__ u64 add2(u64 a, u64 b) {
    u64 d;
    asm("add.rn.f32x2 %0, %1, %2;" : "=l"(d) : "l"(a), "l"(b));
    return d;
}
static __device__ __forceinline__ u64 pack2(float lo, float hi) {
    u64 d;
    asm("mov.b64 %0, {%1, %2};" : "=l"(d) : "f"(lo), "f"(hi));
    return d;
}
static __device__ __forceinline__ void unpack2(u64 v, float& lo, float& hi) {
    asm("mov.b64 {%0, %1}, %2;" : "=f"(lo), "=f"(hi) : "l"(v));
}
static __device__ __forceinline__ float ldcg(const float* p) {
    float v;
    asm volatile("ld.global.cg.f32 %0, [%1];" : "=f"(v) : "l"(p));
    return v;
}
static __device__ __forceinline__ float warp_sum(float v) {
    #pragma unroll
    for (int off = 16; off > 0; off >>= 1)
        v += __shfl_xor_sync(0xffffffffu, v, off);
    return v;
}
static __device__ __forceinline__ int warp_sum_i(int v) {
    #pragma unroll
    for (int off = 16; off > 0; off >>= 1)
        v += __shfl_xor_sync(0xffffffffu, v, off);
    return v;
}

__global__ void prep_kernel(const float* __restrict__ trans) {
    int i = blockIdx.x * blockDim.x + threadIdx.x;   // 0..4095
    float e = __expf(trans[i]);
    g_expE[i] = e;
    g_expET[(i & (Tt - 1)) * Tt + (i >> 6)] = e;
}

__global__ __launch_bounds__(32, 14) void crf_kernel(
    const float* __restrict__ feats,
    const unsigned char* __restrict__ mask8,
    const int* __restrict__ tags,
    const float* __restrict__ trans,
    float* __restrict__ out)
{
    const int role = blockIdx.x >> 9;          // 0..3
    const int b    = blockIdx.x & (Bb - 1);
    const int lane = threadIdx.x;
    const int to0  = 2 * lane;

    __shared__ __align__(16) float qbuf[2][Tt];

    // ---- mask layout probe (uint8 vs int32) + sequence length ----
    const int* mask32 = reinterpret_cast<const int*>(mask8);
    const bool is32 = (mask8[0] == 1 && mask8[1] == 0 && mask8[2] == 0 && mask8[3] == 0);

    int cnt = 0;
    #pragma unroll
    for (int k = 0; k < Ss / 32; ++k) {
        int s  = lane + k * 32;
        int mv = is32 ? mask32[b * Ss + s] : (int)mask8[b * Ss + s];
        cnt += (mv != 0);
    }
    const int L  = warp_sum_i(cnt);            // >= 256
    const int aB = L / 3;                      // >= 85
    const int bB = (2 * L) / 3;

    const float* fb = feats + (size_t)b * Ss * Tt;

    // ---- E registers (rows of chosen orientation, from precomputed exp) ----
    const float* Es = (role < 2) ? g_expET : g_expE;
    u64 E2a[Tt / 2], E2b[Tt / 2];
    {
        const float4* ra = reinterpret_cast<const float4*>(Es + to0 * Tt);
        const float4* rb = reinterpret_cast<const float4*>(Es + (to0 + 1) * Tt);
        #pragma unroll
        for (int k = 0; k < 16; ++k) {
            float4 v = ra[k];
            E2a[2 * k]     = pack2(v.x, v.y);
            E2a[2 * k + 1] = pack2(v.z, v.w);
            float4 u = rb[k];
            E2b[2 * k]     = pack2(u.x, u.y);
            E2b[2 * k + 1] = pack2(u.z, u.w);
        }
    }

    int   eSum = 0;
    int   pb   = 0;
    float cur0 = 0.f, cur1 = 0.f;
    float c0v  = 0.f, goldv = 0.f;

    // fwd: q_new = (E^T q) * ef * 2^k ; raw feats, exp at consume time
    auto fstep = [&](float2 f) {
        const float ea  = __expf(f.x);
        const float eb2 = __expf(f.y);
        __syncwarp();
        const ulonglong2* qp = reinterpret_cast<const ulonglong2*>(qbuf[pb]);
        ulonglong2 v = qp[0];
        float q0, td;
        unpack2(v.x, q0, td);
        u64 x0 = fma2(v.x, E2a[0], 0ull), x1 = fma2(v.y, E2a[1], 0ull);
        u64 y0 = fma2(v.x, E2b[0], 0ull), y1 = fma2(v.y, E2b[1], 0ull);
        #pragma unroll
        for (int j = 1; j < 16; ++j) {
            v = qp[j];
            x0 = fma2(v.x, E2a[2 * j],     x0);
            x1 = fma2(v.y, E2a[2 * j + 1], x1);
            y0 = fma2(v.x, E2b[2 * j],     y0);
            y1 = fma2(v.y, E2b[2 * j + 1], y1);
        }
        const unsigned ebits = __float_as_uint(q0) >> 23;
        eSum += (int)ebits - 127;
        const float sc = __uint_as_float((254u - ebits) << 23);
        float lo, hi;
        unpack2(add2(x0, x1), lo, hi); cur0 = (lo + hi) * (ea * sc);
        unpack2(add2(y0, y1), lo, hi); cur1 = (lo + hi) * (eb2 * sc);
        pb ^= 1;
        *reinterpret_cast<float2*>(&qbuf[pb][to0]) = make_float2(cur0, cur1);
    };
    // bwd: w_new = (E w) * 2^k ; store carries * ef of the NEXT consumed row
    auto bstep = [&](float2 f) {
        const float ea  = __expf(f.x);
        const float eb2 = __expf(f.y);
        __syncwarp();
        const ulonglong2* qp = reinterpret_cast<const ulonglong2*>(qbuf[pb]);
        ulonglong2 v = qp[0];
        float w0, td;
        unpack2(v.x, w0, td);
        u64 x0 = fma2(v.x, E2a[0], 0ull), x1 = fma2(v.y, E2a[1], 0ull);
        u64 y0 = fma2(v.x, E2b[0], 0ull), y1 = fma2(v.y, E2b[1], 0ull);
        #pragma unroll
        for (int j = 1; j < 16; ++j) {
            v = qp[j];
            x0 = fma2(v.x, E2a[2 * j],     x0);
            x1 = fma2(v.y, E2a[2 * j + 1], x1);
            y0 = fma2(v.x, E2b[2 * j],     y0);
            y1 = fma2(v.y, E2b[2 * j + 1], y1);
        }
        const unsigned ebits = __float_as_uint(w0) >> 23;
        eSum += (int)ebits - 127;
        const float sc = __uint_as_float((254u - ebits) << 23);
        float lo, hi;
        unpack2(add2(x0, x1), lo, hi); cur0 = (lo + hi) * sc;
        unpack2(add2(y0, y1), lo, hi); cur1 = (lo + hi) * sc;
        pb ^= 1;
        *reinterpret_cast<float2*>(&qbuf[pb][to0]) = make_float2(cur0 * ea, cur1 * eb2);
    };

    // ---- scan drivers with RAW float2 ring (PD-step LDG->use distance) ----
    auto fwd_scan = [&](int first, int last) {
        float2 fp[PD];
        #pragma unroll
        for (int r = 0; r < PD; ++r)
            fp[r] = *reinterpret_cast<const float2*>(fb + (size_t)(first + r) * Tt + to0);
        int s = first;
        for (; s + (PD - 1) <= last; ) {
            #pragma unroll
            for (int r = 0; r < PD; ++r) {
                const float2 f = fp[r];
                fp[r] = *reinterpret_cast<const float2*>(fb + (size_t)(s + PD) * Tt + to0);
                fstep(f);
                ++s;
            }
        }
        for (; s <= last; ++s) {
            int r = (s - first) & (PD - 1);
            fstep(fp[r]);
        }
    };
    auto bwd_scan = [&](int top, int n) {
        float2 fp[PD];
        #pragma unroll
        for (int r = 0; r < PD; ++r)
            fp[r] = *reinterpret_cast<const float2*>(fb + (size_t)(top - 1 - r) * Tt + to0);
        int j = 0;
        for (; j + PD <= n; ) {
            #pragma unroll
            for (int r = 0; r < PD; ++r) {
                const float2 f = fp[r];
                fp[r] = *reinterpret_cast<const float2*>(
                    fb + (size_t)(top - 1 - j - PD) * Tt + to0);
                bstep(f);
                ++j;
            }
        }
        for (; j < n; ++j) {
            int r = j & (PD - 1);
            bstep(fp[r]);
        }
    };

    if (role == 0) {
        const int* tg = tags + b * Ss;
        float gsum = 0.f;
        for (int s = lane; s < L; s += 32) {
            int t1 = tg[s];
            int t0 = (s == 0) ? START : tg[s - 1];
            gsum += fb[s * Tt + t1] + trans[t0 * Tt + t1];
        }
        goldv = warp_sum(gsum) + trans[tg[L - 1] * Tt + STOP];

        c0v = fb[0] + trans[START * Tt];
        float2 f0 = *reinterpret_cast<const float2*>(fb + to0);
        qbuf[0][to0]     = __expf(f0.x + trans[START * Tt + to0]     - c0v);
        qbuf[0][to0 + 1] = __expf(f0.y + trans[START * Tt + to0 + 1] - c0v);
        fwd_scan(1, aB);
    } else if (role == 1) {
        qbuf[0][to0] = 1.f;  qbuf[0][to0 + 1] = 1.f;
        fwd_scan(aB + 1, bB);
    } else if (role == 2) {
        float2 f0 = *reinterpret_cast<const float2*>(fb + (size_t)bB * Tt + to0);
        qbuf[0][to0]     = __expf(f0.x);
        qbuf[0][to0 + 1] = __expf(f0.y);
        bwd_scan(bB, bB - aB);
    } else {
        float lo, u0, u1;
        unpack2(E2a[31], lo, u0);   // E[to0][STOP]
        unpack2(E2b[31], lo, u1);   // E[to0+1][STOP]
        cur0 = u0;  cur1 = u1;
        float2 f0 = *reinterpret_cast<const float2*>(fb + (size_t)(L - 1) * Tt + to0);
        qbuf[0][to0]     = u0 * __expf(f0.x);
        qbuf[0][to0 + 1] = u1 * __expf(f0.y);
        bwd_scan(L - 1, L - 1 - bB);
    }

    // ---- publish ----
    {
        float* m = g_meet[b][role];
        m[to0]     = cur0;
        m[to0 + 1] = cur1;
        if (lane == 0) {
            m[64] = (float)eSum;
            if (role == 0) { m[65] = c0v; m[66] = goldv; }
        }
    }

    // ---- rendezvous: 4th arriver combines ----
    __threadfence();
    unsigned old = 0;
    if (lane == 0) old = atomicAdd(&g_pair[b], 1u);
    old = __shfl_sync(0xffffffffu, old, 0);
    if (old != 3u) return;

    __threadfence();
    const float p0  = ldcg(&g_meet[b][0][to0]);
    const float p1  = ldcg(&g_meet[b][0][to0 + 1]);
    const float uu0 = ldcg(&g_meet[b][1][to0]);
    const float uu1 = ldcg(&g_meet[b][1][to0 + 1]);
    const float v0  = ldcg(&g_meet[b][2][to0]);
    const float v1  = ldcg(&g_meet[b][2][to0 + 1]);
    const float t0  = ldcg(&g_meet[b][3][to0]);
    const float t1  = ldcg(&g_meet[b][3][to0 + 1]);
    const float dot1 = warp_sum(v0 * p0 + v1 * p1);     // v^T P
    const float dot2 = warp_sum(t0 * uu0 + t1 * uu1);   // t^T u
    const float den  = warp_sum(uu0 + uu1);             // e^T u

    unsigned c = 0;
    if (lane == 0) {
        const float S0 = ldcg(&g_meet[b][0][64]);
        const float S2 = ldcg(&g_meet[b][2][64]);
        const float S3 = ldcg(&g_meet[b][3][64]);
        const float c0 = ldcg(&g_meet[b][0][65]);
        const float gv = ldcg(&g_meet[b][0][66]);
        const float logZ = c0 + (S0 + S2 + S3) * LN2
                         + __logf(dot1) + __logf(dot2) - __logf(den);
        g_partial[b] = logZ - gv;
        g_pair[b] = 0;
        __threadfence();
        c = atomicAdd(&g_count, 1u);
    }
    c = __shfl_sync(0xffffffffu, c, 0);

    if (c == (unsigned)(Bb - 1)) {
        __threadfence();
        float sum = 0.f;
        #pragma unroll
        for (int k = 0; k < Bb / 32; ++k)
            sum += ldcg(&g_partial[lane + k * 32]);
        sum = warp_sum(sum);
        if (lane == 0) {
            out[0] = sum;
            g_count = 0;
        }
    }
}

extern "C" void kernel_launch(void* const* d_in, const int* in_sizes, int n_in,
                              void* d_out, int out_size)
{
    (void)in_sizes; (void)n_in; (void)out_size;
    const float*         feats = (const float*)d_in[0];
    const unsigned char* mask  = (const unsigned char*)d_in[1];
    const int*           tags  = (const int*)d_in[2];
    const float*         trans = (const float*)d_in[3];

    prep_kernel<<<4, 1024>>>(trans);
    crf_kernel<<<4 * Bb, 32>>>(feats, mask, tags, trans, (float*)d_out);
}

// round 15
// speedup vs baseline: 3.1185x; 3.1185x over previous
#include <cuda_runtime.h>

// CRF NLL, bidirectional exp-domain scan, single-warp chains (R13 topology),
// matvec in BF16 via HFMA2 (fma.rn.bf16x2): rt=2 vs f32x2's RF-bank rt=3,
// half the LDS, E in 64 regs. Exact power-of-2 rescaling from the bf16
// exponent field keeps the log bookkeeping exact; bf16 quantization adds
// ~1e-5..1e-4 rel err (threshold 1e-3). Raw feats ring, exp at consume time.
// 1024 blocks x 32 threads: block b (<512) = forward half (P_h);
// block b+512 = backward co-vector half (u_h). answer = log(dot(P_h,u_h)).

constexpr int Bb = 512;
constexpr int Ss = 512;
constexpr int Tt = 64;
constexpr int START = Tt - 2;
constexpr int STOP  = Tt - 1;
constexpr int PD    = 4;     // feats prefetch depth (steps)
constexpr float LN2 = 0.69314718055994531f;

__device__ float g_meet[Bb][2][68];  // [0]: P_h,64=eF,65=c0,66=goldF ; [1]: u_h,64=eB,65=goldB
__device__ float g_partial[Bb];
__device__ unsigned g_pair[Bb];      // zero-initialized
__device__ unsigned g_count = 0;

static __device__ __forceinline__ unsigned hfma2(unsigned a, unsigned b, unsigned c) {
    unsigned d;
    asm("fma.rn.bf16x2 %0, %1, %2, %3;" : "=r"(d) : "r"(a), "r"(b), "r"(c));
    return d;
}
static __device__ __forceinline__ unsigned hadd2(unsigned a, unsigned b) {
    unsigned d;
    asm("add.rn.bf16x2 %0, %1, %2;" : "=r"(d) : "r"(a), "r"(b));
    return d;
}
// pack two f32 into bf16x2: result.lo = lo, result.hi = hi
static __device__ __forceinline__ unsigned pack_bf2(float lo, float hi) {
    unsigned d;
    asm("cvt.rn.bf16x2.f32 %0, %1, %2;" : "=r"(d) : "f"(hi), "f"(lo));
    return d;
}
static __device__ __forceinline__ float bf_lo(unsigned w) {
    return __uint_as_float(w << 16);
}
static __device__ __forceinline__ float bf_hi(unsigned w) {
    return __uint_as_float(w & 0xFFFF0000u);
}
static __device__ __forceinline__ float ldcg(const float* p) {
    float v;
    asm volatile("ld.global.cg.f32 %0, [%1];" : "=f"(v) : "l"(p));
    return v;
}
static __device__ __forceinline__ float warp_sum(float v) {
    #pragma unroll
    for (int off = 16; off > 0; off >>= 1)
        v += __shfl_xor_sync(0xffffffffu, v, off);
    return v;
}
static __device__ __forceinline__ int warp_sum_i(int v) {
    #pragma unroll
    for (int off = 16; off > 0; off >>= 1)
        v += __shfl_xor_sync(0xffffffffu, v, off);
    return v;
}

__global__ __launch_bounds__(32) void crf_kernel(
    const float* __restrict__ feats,
    const unsigned char* __restrict__ mask8,
    const int* __restrict__ tags,
    const float* __restrict__ trans,
    float* __restrict__ out)
{
    const bool isF = (blockIdx.x < Bb);
    const int  b   = isF ? blockIdx.x : blockIdx.x - Bb;
    const int  lane = threadIdx.x;      // 0..31
    const int  to0  = 2 * lane;         // owned tags

    __shared__ __align__(16) unsigned qbuf[2][Tt / 2];   // bf16x2 per tag-pair

    // ---- mask layout probe (uint8 vs int32) + sequence length ----
    const int* mask32 = reinterpret_cast<const int*>(mask8);
    const bool is32 = (mask8[0] == 1 && mask8[1] == 0 && mask8[2] == 0 && mask8[3] == 0);

    int cnt = 0;
    #pragma unroll
    for (int k = 0; k < Ss / 32; ++k) {
        int s  = lane + k * 32;
        int mv = is32 ? mask32[b * Ss + s] : (int)mask8[b * Ss + s];
        cnt += (mv != 0);
    }
    const int L = warp_sum_i(cnt);   // >= 256
    const int h = L / 2;             // forward: steps 1..h ; backward: L-1..h+1

    const float* fb = feats + (size_t)b * Ss * Tt;
    const int*   tg = tags + b * Ss;

    float goldv = 0.f, c0f = 0.f;
    int   eSum = 0;
    float cur0 = 0.f, cur1 = 0.f;

    // ---- E as bf16x2 pairs over FROM for both owned tags ----
    unsigned E2a[Tt / 2], E2b[Tt / 2];
    if (isF) {
        #pragma unroll
        for (int k = 0; k < Tt / 2; ++k) {
            E2a[k] = pack_bf2(__expf(trans[(2 * k) * Tt + to0]),
                              __expf(trans[(2 * k + 1) * Tt + to0]));
            E2b[k] = pack_bf2(__expf(trans[(2 * k) * Tt + to0 + 1]),
                              __expf(trans[(2 * k + 1) * Tt + to0 + 1]));
        }
    } else {
        #pragma unroll
        for (int k = 0; k < Tt / 2; ++k) {
            E2a[k] = pack_bf2(__expf(trans[to0 * Tt + 2 * k]),
                              __expf(trans[to0 * Tt + 2 * k + 1]));
            E2b[k] = pack_bf2(__expf(trans[(to0 + 1) * Tt + 2 * k]),
                              __expf(trans[(to0 + 1) * Tt + 2 * k + 1]));
        }
    }

    int pb = 0;   // current qbuf index

    // shared matvec: dotA/dotB for the two owned tags; w0 = first u32 word
    auto matvec = [&](float& dotA, float& dotB, unsigned& w0) {
        const uint4* qp = reinterpret_cast<const uint4*>(qbuf[pb]);
        unsigned aA0, aA1, aA2, aA3, aB0, aB1, aB2, aB3;
        {
            uint4 v = qp[0];
            w0 = v.x;
            aA0 = hfma2(v.x, E2a[0], 0u);
            aA1 = hfma2(v.y, E2a[1], 0u);
            aA2 = hfma2(v.z, E2a[2], 0u);
            aA3 = hfma2(v.w, E2a[3], 0u);
            aB0 = hfma2(v.x, E2b[0], 0u);
            aB1 = hfma2(v.y, E2b[1], 0u);
            aB2 = hfma2(v.z, E2b[2], 0u);
            aB3 = hfma2(v.w, E2b[3], 0u);
        }
        #pragma unroll
        for (int j = 1; j < 8; ++j) {
            uint4 v = qp[j];
            aA0 = hfma2(v.x, E2a[4 * j + 0], aA0);
            aA1 = hfma2(v.y, E2a[4 * j + 1], aA1);
            aA2 = hfma2(v.z, E2a[4 * j + 2], aA2);
            aA3 = hfma2(v.w, E2a[4 * j + 3], aA3);
            aB0 = hfma2(v.x, E2b[4 * j + 0], aB0);
            aB1 = hfma2(v.y, E2b[4 * j + 1], aB1);
            aB2 = hfma2(v.z, E2b[4 * j + 2], aB2);
            aB3 = hfma2(v.w, E2b[4 * j + 3], aB3);
        }
        const unsigned sA = hadd2(hadd2(aA0, aA1), hadd2(aA2, aA3));
        const unsigned sB = hadd2(hadd2(aB0, aB1), hadd2(aB2, aB3));
        dotA = bf_lo(sA) + bf_hi(sA);
        dotB = bf_lo(sB) + bf_hi(sB);
    };

    if (isF) {
        // ---- gold score, FIRST half [0, h) ----
        float gsum = 0.f;
        for (int s = lane; s < h; s += 32) {
            int t1 = tg[s];
            int t0 = (s == 0) ? START : tg[s - 1];
            gsum += fb[s * Tt + t1] + trans[t0 * Tt + t1];
        }
        goldv = warp_sum(gsum);

        // ---- init: P_0 = exp(f_0 + T[START,:]), normalized by c0 ----
        const float c0 = fb[0] + trans[START * Tt];
        c0f = c0;
        {
            float2 f0 = *reinterpret_cast<const float2*>(fb + to0);
            qbuf[0][lane] = pack_bf2(__expf(f0.x + trans[START * Tt + to0]     - c0),
                                     __expf(f0.y + trans[START * Tt + to0 + 1] - c0));
        }

        float2 fp[PD];
        #pragma unroll
        for (int r = 0; r < PD; ++r)
            fp[r] = *reinterpret_cast<const float2*>(fb + (1 + r) * Tt + to0);

        auto step = [&](float2 f) {
            const float ea = __expf(f.x);
            const float eb = __expf(f.y);
            __syncwarp();
            float dA, dB;
            unsigned w0;
            matvec(dA, dB, w0);
            const unsigned e = (w0 >> 7) & 0xFFu;   // bf16 exponent of q[0]
            eSum += (int)e - 127;
            const float scale = __uint_as_float((254u - e) << 23);
            cur0 = dA * (ea * scale);
            cur1 = dB * (eb * scale);
            pb ^= 1;
            qbuf[pb][lane] = pack_bf2(cur0, cur1);
        };

        const int end = h + 1;   // steps 1..h
        int s = 1;
        for (; s + (PD - 1) < end; ) {
            #pragma unroll
            for (int r = 0; r < PD; ++r) {
                const float2 f = fp[r];
                fp[r] = *reinterpret_cast<const float2*>(fb + (s + PD) * Tt + to0);
                step(f);
                ++s;
            }
        }
        for (; s < end; ++s) step(fp[(s - 1) & (PD - 1)]);

        // ---- publish P_h ----
        g_meet[b][0][to0]     = cur0;
        g_meet[b][0][to0 + 1] = cur1;
        if (lane == 0) {
            g_meet[b][0][64] = (float)eSum;
            g_meet[b][0][65] = c0f;
            g_meet[b][0][66] = goldv;
        }
    } else {
        // ---- gold score, SECOND half [h, L) + STOP transition ----
        float gsum = 0.f;
        for (int s = h + lane; s < L; s += 32) {
            int t1 = tg[s];
            int t0 = tg[s - 1];   // s >= h >= 128 > 0
            gsum += fb[s * Tt + t1] + trans[t0 * Tt + t1];
        }
        goldv = warp_sum(gsum) + trans[tg[L - 1] * Tt + STOP];

        // ---- backward: u_{L-1} = Estop; w_t = u_t . ef_t; u_{t-1} = E w_t ----
        {
            float2 f0 = *reinterpret_cast<const float2*>(fb + (size_t)(L - 1) * Tt + to0);
            cur0 = __expf(trans[to0 * Tt + STOP]);
            cur1 = __expf(trans[(to0 + 1) * Tt + STOP]);
            qbuf[0][lane] = pack_bf2(cur0 * __expf(f0.x), cur1 * __expf(f0.y));
        }

        const int nB = L - 1 - h;   // >= 127
        float2 fp[PD];
        #pragma unroll
        for (int r = 0; r < PD; ++r)
            fp[r] = *reinterpret_cast<const float2*>(fb + (size_t)(L - 2 - r) * Tt + to0);

        auto bstep = [&](float2 f) {
            const float ea = __expf(f.x);
            const float eb = __expf(f.y);
            __syncwarp();
            float dA, dB;
            unsigned w0;
            matvec(dA, dB, w0);
            const unsigned e = (w0 >> 7) & 0xFFu;
            eSum += (int)e - 127;
            const float scale = __uint_as_float((254u - e) << 23);
            cur0 = dA * scale;          // u_{t-1}[to0]
            cur1 = dB * scale;
            pb ^= 1;
            qbuf[pb][lane] = pack_bf2(cur0 * ea, cur1 * eb);
        };

        int j = 0;
        for (; j + (PD - 1) < nB; ) {
            #pragma unroll
            for (int r = 0; r < PD; ++r) {
                const float2 f = fp[r];
                fp[r] = *reinterpret_cast<const float2*>(
                    fb + (size_t)(L - 2 - j - PD) * Tt + to0);
                bstep(f);
                ++j;
            }
        }
        for (; j < nB; ++j) bstep(fp[j & (PD - 1)]);

        // ---- publish u_h ----
        g_meet[b][1][to0]     = cur0;
        g_meet[b][1][to0 + 1] = cur1;
        if (lane == 0) {
            g_meet[b][1][64] = (float)eSum;
            g_meet[b][1][65] = goldv;
        }
    }

    // ---- pair rendezvous: second arriver combines ----
    __threadfence();
    unsigned old = 0;
    if (lane == 0) old = atomicAdd(&g_pair[b], 1u);
    old = __shfl_sync(0xffffffffu, old, 0);
    if (old != 1u) return;   // first arriver exits

    __threadfence();
    const float* o = &g_meet[b][isF ? 1 : 0][0];
    float dot = warp_sum(cur0 * ldcg(o + to0) + cur1 * ldcg(o + to0 + 1));

    unsigned c = 0;
    if (lane == 0) {
        float eF, eB, c0v, gv;
        if (isF) {
            eF = (float)eSum; c0v = c0f;
            gv = goldv + ldcg(&g_meet[b][1][65]);
            eB = ldcg(&g_meet[b][1][64]);
        } else {
            eB = (float)eSum;
            eF  = ldcg(&g_meet[b][0][64]);
            c0v = ldcg(&g_meet[b][0][65]);
            gv  = goldv + ldcg(&g_meet[b][0][66]);
        }
        g_partial[b] = c0v + (eF + eB) * LN2 + __logf(dot) - gv;
        g_pair[b] = 0;                       // reset for graph replay
        __threadfence();
        c = atomicAdd(&g_count, 1u);
    }
    c = __shfl_sync(0xffffffffu, c, 0);

    // ---- last combiner: deterministic fixed-order reduction over batches ----
    if (c == (unsigned)(Bb - 1)) {
        __threadfence();
        float sum = 0.f;
        #pragma unroll
        for (int k = 0; k < Bb / 32; ++k)
            sum += ldcg(&g_partial[lane + k * 32]);
        sum = warp_sum(sum);
        if (lane == 0) {
            out[0] = sum;
            g_count = 0;                     // reset for graph replay
        }
    }
}

extern "C" void kernel_launch(void* const* d_in, const int* in_sizes, int n_in,
                              void* d_out, int out_size)
{
    (void)in_sizes; (void)n_in; (void)out_size;
    const float*         feats = (const float*)d_in[0];
    const unsigned char* mask  = (const unsigned char*)d_in[1];
    const int*           tags  = (const int*)d_in[2];
    const float*         trans = (const float*)d_in[3];

    crf_kernel<<<2 * Bb, 32>>>(feats, mask, tags, trans, (float*)d_out);
}